// round 2
// baseline (speedup 1.0000x reference)
#include <cuda_runtime.h>

#define NMAX 50000
#define EMAX 500000
#define HID 64
#define HO 128
#define NLAYERS 3
#define NFEAT 266   // 10 + 4*64

// ---------------- device scratch (static: no allocation allowed) ----------------
__device__ float g_h[4][NMAX * HID];      // h0..h3
__device__ float g_fni[NMAX * HO];
__device__ float g_fnj[NMAX * HO];
__device__ float g_hw[NMAX * HO];
__device__ float g_hatt[NMAX * HO];
__device__ float g_z[NMAX * HO];
__device__ float g_e[EMAX * 2];
__device__ float g_ex[EMAX * 2];
__device__ unsigned g_nmax[NMAX * 2];
__device__ float g_nsum[NMAX * 2];
__device__ float g_tab[44 * HO];          // folded edge tables (per layer, rewritten)
__device__ unsigned g_gmax[8 * NFEAT];    // per-graph pooled max (encoded)

// orderable-uint encoding of float for atomicMax
__device__ __forceinline__ unsigned encf(float x) {
    unsigned u = __float_as_uint(x);
    return (u & 0x80000000u) ? ~u : (u | 0x80000000u);
}
__device__ __forceinline__ float decf(unsigned u) {
    u = (u & 0x80000000u) ? (u & 0x7fffffffu) : ~u;
    return __uint_as_float(u);
}

// ---------------- initial node MLP: h0 = relu(feat@W0+b0)@W1+b1 ----------------
__global__ void k_h0(const float* __restrict__ feat,
                     const float* __restrict__ W0, const float* __restrict__ b0,
                     const float* __restrict__ W1, const float* __restrict__ b1, int n) {
    __shared__ float sW0[10 * HID], sW1[HID * HID], sb0[HID], sb1[HID], sz[4][HID];
    for (int i = threadIdx.x; i < 10 * HID; i += blockDim.x) sW0[i] = W0[i];
    for (int i = threadIdx.x; i < HID * HID; i += blockDim.x) sW1[i] = W1[i];
    if (threadIdx.x < HID) { sb0[threadIdx.x] = b0[threadIdx.x]; sb1[threadIdx.x] = b1[threadIdx.x]; }
    __syncthreads();
    int rt = threadIdx.x >> 6, c = threadIdx.x & 63;
    for (int base = blockIdx.x * 4; base < n; base += gridDim.x * 4) {
        int row = base + rt;
        float z = 0.f;
        if (row < n) {
            z = sb0[c];
            #pragma unroll
            for (int k = 0; k < 10; k++) z += feat[row * 10 + k] * sW0[k * HID + c];
            z = fmaxf(z, 0.f);
        }
        sz[rt][c] = z;
        __syncthreads();
        if (row < n) {
            float h = sb1[c];
            #pragma unroll 8
            for (int k = 0; k < HID; k++) h += sz[rt][k] * sW1[k * HID + c];
            g_h[0][row * HID + c] = h;
        }
        __syncthreads();
    }
}

// ---------------- folded edge tables for one layer ----------------
// rows: [0,7) etype_emb@Wf, [7,38) rid_emb@Wf, [38,40) rc_W@Wf, [40,43) rp_W@Wf,
//       [43] (rc_b+rp_b)@Wf + egat_bias
__global__ void k_tables(const float* __restrict__ et_emb, const float* __restrict__ rid_emb,
                         const float* __restrict__ rcW, const float* __restrict__ rpW,
                         const float* __restrict__ rcb, const float* __restrict__ rpb,
                         const float* __restrict__ Wf, const float* __restrict__ ebias) {
    int r = blockIdx.x, c = threadIdx.x;
    float acc = 0.f;
    if (r < 43) {
        const float* vrow;
        if (r < 7)       vrow = et_emb + r * HID;
        else if (r < 38) vrow = rid_emb + (r - 7) * HID;
        else if (r < 40) vrow = rcW + (r - 38) * HID;
        else             vrow = rpW + (r - 40) * HID;
        #pragma unroll 8
        for (int k = 0; k < HID; k++) acc += vrow[k] * Wf[k * HO + c];
    } else {
        acc = ebias[c];
        #pragma unroll 8
        for (int k = 0; k < HID; k++) acc += (rcb[k] + rpb[k]) * Wf[k * HO + c];
    }
    g_tab[r * HO + c] = acc;
}

// ---------------- per-layer reset ----------------
__global__ void k_zero_layer(int n) {
    int i = blockIdx.x * blockDim.x + threadIdx.x;
    if (i < n * HO) g_hatt[i] = 0.f;
    if (i < n * 2) { g_nmax[i] = 0u; g_nsum[i] = 0.f; }
}

// ---------------- generic small-K node GEMM: C = [relu](A@W + bias) [+ skip] ----------------
template<int K, int M, bool RELU, bool SKIP, bool BIAS>
__global__ void k_gemm(const float* __restrict__ A, const float* __restrict__ W,
                       const float* __restrict__ bias, const float* __restrict__ skip,
                       float* __restrict__ C, int n) {
    constexpr int CJ = M / 16;
    __shared__ float As[64 * 33];
    __shared__ float Ws[32 * M];
    int tid = threadIdx.x;
    int ty = tid >> 4, tx = tid & 15;
    int rowBase = blockIdx.x * 64;
    float acc[4][CJ];
    #pragma unroll
    for (int i = 0; i < 4; i++)
        #pragma unroll
        for (int j = 0; j < CJ; j++) acc[i][j] = 0.f;

    for (int kc = 0; kc < K; kc += 32) {
        int rr0 = tid >> 5;
        int kk = tid & 31;
        #pragma unroll
        for (int s = 0; s < 8; s++) {
            int r = rr0 + s * 8;
            int row = rowBase + r;
            As[r * 33 + kk] = (row < n) ? A[row * K + kc + kk] : 0.f;
        }
        #pragma unroll
        for (int idx = tid; idx < 32 * M; idx += 256) {
            int kw = idx / M, m = idx % M;
            Ws[kw * M + m] = W[(kc + kw) * M + m];
        }
        __syncthreads();
        #pragma unroll
        for (int k2 = 0; k2 < 32; k2++) {
            float a[4], w[CJ];
            #pragma unroll
            for (int i = 0; i < 4; i++) a[i] = As[(ty * 4 + i) * 33 + k2];
            #pragma unroll
            for (int j = 0; j < CJ; j++) w[j] = Ws[k2 * M + tx + 16 * j];
            #pragma unroll
            for (int i = 0; i < 4; i++)
                #pragma unroll
                for (int j = 0; j < CJ; j++) acc[i][j] += a[i] * w[j];
        }
        __syncthreads();
    }
    #pragma unroll
    for (int i = 0; i < 4; i++) {
        int row = rowBase + ty * 4 + i;
        if (row >= n) continue;
        #pragma unroll
        for (int j = 0; j < CJ; j++) {
            int c = tx + 16 * j;
            float v = acc[i][j];
            if (BIAS) v += bias[c];
            if (RELU) v = fmaxf(v, 0.f);
            if (SKIP) v += skip[row * M + c];
            C[row * M + c] = v;
        }
    }
}

// ---------------- edge pass A: attention logits e + per-dst atomicMax ----------------
__global__ void k_edgeA(const float* __restrict__ attrc, const float* __restrict__ attrp,
                        const int* __restrict__ etype, const int* __restrict__ rid,
                        const int* __restrict__ src, const int* __restrict__ dst,
                        const float* __restrict__ attn, int E) {
    __shared__ float sT[44 * HO];
    __shared__ float sA[HO];
    for (int i = threadIdx.x; i < 44 * HO; i += blockDim.x) sT[i] = g_tab[i];
    for (int i = threadIdx.x; i < HO; i += blockDim.x) sA[i] = attn[i];
    __syncthreads();
    const float* sR  = sT + 7 * HO;
    const float* sRC = sT + 38 * HO;
    const float* sRP = sT + 40 * HO;
    const float* sB  = sT + 43 * HO;
    int lane = threadIdx.x & 31;
    int warp = (blockIdx.x * blockDim.x + threadIdx.x) >> 5;
    int nw = (gridDim.x * blockDim.x) >> 5;
    for (int e = warp; e < E; e += nw) {
        int s = src[e], d = dst[e];
        int et = etype[e], rr = rid[e];
        float rc0 = attrc[e * 2 + 0], rc1 = attrc[e * 2 + 1];
        float rp0 = attrp[e * 3 + 0], rp1 = attrp[e * 3 + 1], rp2 = attrp[e * 3 + 2];
        const float* te = sT + et * HO;
        const float* re = sR + rr * HO;
        float p0 = 0.f, p1 = 0.f;
        #pragma unroll
        for (int j = 0; j < 4; j++) {
            int c = lane + 32 * j;
            float v = g_fni[s * HO + c] + g_fnj[d * HO + c] + te[c] + re[c]
                    + rc0 * sRC[c] + rc1 * sRC[HO + c]
                    + rp0 * sRP[c] + rp1 * sRP[HO + c] + rp2 * sRP[2 * HO + c]
                    + sB[c];
            v = (v > 0.f) ? v : 0.2f * v;  // leaky_relu(0.2)
            float pv = v * sA[c];
            if (j < 2) p0 += pv; else p1 += pv;
        }
        #pragma unroll
        for (int o = 16; o > 0; o >>= 1) {
            p0 += __shfl_xor_sync(0xffffffffu, p0, o);
            p1 += __shfl_xor_sync(0xffffffffu, p1, o);
        }
        if (lane == 0) {
            g_e[e * 2 + 0] = p0;
            g_e[e * 2 + 1] = p1;
            atomicMax(&g_nmax[d * 2 + 0], encf(p0));
            atomicMax(&g_nmax[d * 2 + 1], encf(p1));
        }
    }
}

// ---------------- edge pass B: exp + per-dst sum ----------------
__global__ void k_edgeB(const int* __restrict__ dst, int E) {
    int e = blockIdx.x * blockDim.x + threadIdx.x;
    if (e >= E) return;
    int d = dst[e];
    #pragma unroll
    for (int h = 0; h < 2; h++) {
        float m = decf(g_nmax[d * 2 + h]);
        float ex = __expf(g_e[e * 2 + h] - m);
        g_ex[e * 2 + h] = ex;
        atomicAdd(&g_nsum[d * 2 + h], ex);
    }
}

// ---------------- edge pass C: weighted scatter to h_att ----------------
__global__ void k_edgeC(const int* __restrict__ src, const int* __restrict__ dst, int E) {
    int lane = threadIdx.x & 31;
    int e = (blockIdx.x * blockDim.x + threadIdx.x) >> 5;
    if (e >= E) return;
    int s = src[e], d = dst[e];
    float a0 = g_ex[e * 2 + 0] / (g_nsum[d * 2 + 0] + 1e-9f);
    float a1 = g_ex[e * 2 + 1] / (g_nsum[d * 2 + 1] + 1e-9f);
    #pragma unroll
    for (int j = 0; j < 4; j++) {
        int c = lane + 32 * j;
        float al = (j < 2) ? a0 : a1;
        atomicAdd(&g_hatt[d * HO + c], al * g_hw[s * HO + c]);
    }
}

// ---------------- pooling + output ----------------
__device__ __forceinline__ float getFeat(int node, int f, const float* __restrict__ feat) {
    if (f < 10) return feat[node * 10 + f];
    int a = (f - 10) >> 6, c = (f - 10) & 63;
    return g_h[a][node * HID + c];
}

__global__ void k_zero_pool() {
    int i = blockIdx.x * blockDim.x + threadIdx.x;
    if (i < 8 * NFEAT) g_gmax[i] = 0u;
}

__global__ void k_pool(const float* __restrict__ feat, int npg) {
    int b = blockIdx.x >> 5;
    int part = blockIdx.x & 31;
    int t = threadIdx.x;
    if (t >= NFEAT) return;
    int per = (npg + 31) / 32;
    int n0 = part * per;
    int n1 = min(n0 + per, npg);
    float m = -3.4e38f;
    for (int nn = n0; nn < n1; nn++)
        m = fmaxf(m, getFeat(b * npg + nn, t, feat));
    if (n1 > n0) atomicMax(&g_gmax[b * NFEAT + t], encf(m));
}

__global__ void k_out(const float* __restrict__ feat, float* __restrict__ out, int npg) {
    int idx = blockIdx.x * blockDim.x + threadIdx.x;
    int tot = 8 * npg * (2 * NFEAT);
    if (idx >= tot) return;
    int c = idx % (2 * NFEAT);
    int nn = idx / (2 * NFEAT);      // global node index (b*npg + n)
    int b = nn / npg;
    float v;
    if (c < NFEAT) v = getFeat(nn, c, feat);
    else           v = decf(g_gmax[b * NFEAT + (c - NFEAT)]);
    out[idx] = v;
}

// ---------------- launch ----------------
extern "C" void kernel_launch(void* const* d_in, const int* in_sizes, int n_in,
                              void* d_out, int out_size) {
    const float* feat  = (const float*)d_in[0];
    const float* attrc = (const float*)d_in[1];
    const float* attrp = (const float*)d_in[2];
    const float* etemb = (const float*)d_in[3];
    const float* ridemb= (const float*)d_in[4];
    const float* rcW   = (const float*)d_in[5];
    const float* rcb   = (const float*)d_in[6];
    const float* rpW   = (const float*)d_in[7];
    const float* rpb   = (const float*)d_in[8];
    const float* feW0  = (const float*)d_in[9];
    const float* feb0  = (const float*)d_in[10];
    const float* feW1  = (const float*)d_in[11];
    const float* feb1  = (const float*)d_in[12];
    const float* Wni   = (const float*)d_in[13];
    const float* Wnj   = (const float*)d_in[14];
    const float* Wfij  = (const float*)d_in[15];
    const float* Wnode = (const float*)d_in[16];
    const float* attn  = (const float*)d_in[17];
    const float* ebias = (const float*)d_in[18];
    const float* Wm0   = (const float*)d_in[19];
    const float* bm0   = (const float*)d_in[20];
    const float* Wm1   = (const float*)d_in[21];
    const float* bm1   = (const float*)d_in[22];
    const int* src   = (const int*)d_in[23];
    const int* dst   = (const int*)d_in[24];
    const int* etype = (const int*)d_in[25];
    const int* rid   = (const int*)d_in[26];

    int N = in_sizes[0] / 10;
    int E = in_sizes[23];
    int npg = N / 8;
    float* out = (float*)d_out;

    void* p;
    cudaGetSymbolAddress(&p, g_h);    float* hbase = (float*)p;
    cudaGetSymbolAddress(&p, g_fni);  float* fni   = (float*)p;
    cudaGetSymbolAddress(&p, g_fnj);  float* fnj   = (float*)p;
    cudaGetSymbolAddress(&p, g_hw);   float* hw    = (float*)p;
    cudaGetSymbolAddress(&p, g_hatt); float* hatt  = (float*)p;
    cudaGetSymbolAddress(&p, g_z);    float* zb    = (float*)p;

    int gb = (N + 63) / 64;

    k_h0<<<512, 256>>>(feat, feW0, feb0, feW1, feb1, N);

    for (int l = 0; l < NLAYERS; l++) {
        const float* hl  = hbase + (size_t)l * NMAX * HID;
        float* hlnext    = hbase + (size_t)(l + 1) * NMAX * HID;

        k_tables<<<44, 128>>>(etemb, ridemb, rcW, rpW, rcb, rpb,
                              Wfij + l * HID * HO, ebias + l * HO);
        k_zero_layer<<<(N * HO + 255) / 256, 256>>>(N);

        k_gemm<64, 128, false, false, false><<<gb, 256>>>(hl, Wni + l * HID * HO, nullptr, nullptr, fni, N);
        k_gemm<64, 128, false, false, false><<<gb, 256>>>(hl, Wnj + l * HID * HO, nullptr, nullptr, fnj, N);
        k_gemm<64, 128, false, false, false><<<gb, 256>>>(hl, Wnode + l * HID * HO, nullptr, nullptr, hw, N);

        k_edgeA<<<1184, 256>>>(attrc, attrp, etype, rid, src, dst, attn + l * HO, E);
        k_edgeB<<<(E + 255) / 256, 256>>>(dst, E);
        k_edgeC<<<(E + 7) / 8, 256>>>(src, dst, E);

        k_gemm<128, 128, true, false, true><<<gb, 256>>>(hatt, Wm0 + l * HO * HO, bm0 + l * HO, nullptr, zb, N);
        k_gemm<128, 64, false, true, true><<<gb, 256>>>(zb, Wm1 + l * HO * HID, bm1 + l * HID, hl, hlnext, N);
    }

    k_zero_pool<<<9, 256>>>();
    k_pool<<<256, 288>>>(feat, npg);
    k_out<<<(8 * npg * 2 * NFEAT + 255) / 256, 256>>>(feat, out, npg);
}

// round 3
// speedup vs baseline: 1.0027x; 1.0027x over previous
#include <cuda_runtime.h>

#define NMAX 50000
#define EMAX 500000
#define HID 64
#define HO 128
#define NLAYERS 3
#define NFEAT 266   // 10 + 4*64

// ---------------- device scratch (static: no allocation allowed) ----------------
__device__ float g_h[4][NMAX * HID];      // h0..h3
__device__ float g_fni[NMAX * HO];
__device__ float g_fnj[NMAX * HO];
__device__ float g_hw[NMAX * HO];
__device__ float g_hatt[NMAX * HO];
__device__ float g_z[NMAX * HO];
__device__ float g_e[EMAX * 2];
__device__ float g_ex[EMAX * 2];
__device__ unsigned g_nmax[NMAX * 2];
__device__ float g_nsum[NMAX * 2];
__device__ float g_tab[44 * HO];          // folded edge tables (per layer, rewritten)
__device__ unsigned g_gmax[8 * NFEAT];    // per-graph pooled max (encoded)

// orderable-uint encoding of float for atomicMax
__device__ __forceinline__ unsigned encf(float x) {
    unsigned u = __float_as_uint(x);
    return (u & 0x80000000u) ? ~u : (u | 0x80000000u);
}
__device__ __forceinline__ float decf(unsigned u) {
    u = (u & 0x80000000u) ? (u & 0x7fffffffu) : ~u;
    return __uint_as_float(u);
}

// ---------------- initial node MLP: h0 = relu(feat@W0+b0)@W1+b1 ----------------
__global__ void k_h0(const float* __restrict__ feat,
                     const float* __restrict__ W0, const float* __restrict__ b0,
                     const float* __restrict__ W1, const float* __restrict__ b1, int n) {
    __shared__ float sW0[10 * HID], sW1[HID * HID], sb0[HID], sb1[HID], sz[4][HID];
    for (int i = threadIdx.x; i < 10 * HID; i += blockDim.x) sW0[i] = W0[i];
    for (int i = threadIdx.x; i < HID * HID; i += blockDim.x) sW1[i] = W1[i];
    if (threadIdx.x < HID) { sb0[threadIdx.x] = b0[threadIdx.x]; sb1[threadIdx.x] = b1[threadIdx.x]; }
    __syncthreads();
    int rt = threadIdx.x >> 6, c = threadIdx.x & 63;
    for (int base = blockIdx.x * 4; base < n; base += gridDim.x * 4) {
        int row = base + rt;
        float z = 0.f;
        if (row < n) {
            z = sb0[c];
            #pragma unroll
            for (int k = 0; k < 10; k++) z += feat[row * 10 + k] * sW0[k * HID + c];
            z = fmaxf(z, 0.f);
        }
        sz[rt][c] = z;
        __syncthreads();
        if (row < n) {
            float h = sb1[c];
            #pragma unroll 8
            for (int k = 0; k < HID; k++) h += sz[rt][k] * sW1[k * HID + c];
            g_h[0][row * HID + c] = h;
        }
        __syncthreads();
    }
}

// ---------------- folded edge tables for one layer ----------------
// rows: [0,7) etype_emb@Wf, [7,38) rid_emb@Wf, [38,40) rc_W@Wf, [40,43) rp_W@Wf,
//       [43] (rc_b+rp_b)@Wf + egat_bias
__global__ void k_tables(const float* __restrict__ et_emb, const float* __restrict__ rid_emb,
                         const float* __restrict__ rcW, const float* __restrict__ rpW,
                         const float* __restrict__ rcb, const float* __restrict__ rpb,
                         const float* __restrict__ Wf, const float* __restrict__ ebias) {
    int r = blockIdx.x, c = threadIdx.x;
    float acc = 0.f;
    if (r < 43) {
        const float* vrow;
        if (r < 7)       vrow = et_emb + r * HID;
        else if (r < 38) vrow = rid_emb + (r - 7) * HID;
        else if (r < 40) vrow = rcW + (r - 38) * HID;
        else             vrow = rpW + (r - 40) * HID;
        #pragma unroll 8
        for (int k = 0; k < HID; k++) acc += vrow[k] * Wf[k * HO + c];
    } else {
        acc = ebias[c];
        #pragma unroll 8
        for (int k = 0; k < HID; k++) acc += (rcb[k] + rpb[k]) * Wf[k * HO + c];
    }
    g_tab[r * HO + c] = acc;
}

// ---------------- per-layer reset ----------------
__global__ void k_zero_layer(int n) {
    int i = blockIdx.x * blockDim.x + threadIdx.x;
    if (i < n * HO) g_hatt[i] = 0.f;
    if (i < n * 2) { g_nmax[i] = 0u; g_nsum[i] = 0.f; }
}

// ---------------- generic small-K node GEMM: C = [relu](A@W + bias) [+ skip] ----------------
template<int K, int M, bool RELU, bool SKIP, bool BIAS>
__global__ void k_gemm(const float* __restrict__ A, const float* __restrict__ W,
                       const float* __restrict__ bias, const float* __restrict__ skip,
                       float* __restrict__ C, int n) {
    constexpr int CJ = M / 16;
    __shared__ float As[64 * 33];
    __shared__ float Ws[32 * M];
    int tid = threadIdx.x;
    int ty = tid >> 4, tx = tid & 15;
    int rowBase = blockIdx.x * 64;
    float acc[4][CJ];
    #pragma unroll
    for (int i = 0; i < 4; i++)
        #pragma unroll
        for (int j = 0; j < CJ; j++) acc[i][j] = 0.f;

    for (int kc = 0; kc < K; kc += 32) {
        int rr0 = tid >> 5;
        int kk = tid & 31;
        #pragma unroll
        for (int s = 0; s < 8; s++) {
            int r = rr0 + s * 8;
            int row = rowBase + r;
            As[r * 33 + kk] = (row < n) ? A[row * K + kc + kk] : 0.f;
        }
        #pragma unroll
        for (int idx = tid; idx < 32 * M; idx += 256) {
            int kw = idx / M, m = idx % M;
            Ws[kw * M + m] = W[(kc + kw) * M + m];
        }
        __syncthreads();
        #pragma unroll
        for (int k2 = 0; k2 < 32; k2++) {
            float a[4], w[CJ];
            #pragma unroll
            for (int i = 0; i < 4; i++) a[i] = As[(ty * 4 + i) * 33 + k2];
            #pragma unroll
            for (int j = 0; j < CJ; j++) w[j] = Ws[k2 * M + tx + 16 * j];
            #pragma unroll
            for (int i = 0; i < 4; i++)
                #pragma unroll
                for (int j = 0; j < CJ; j++) acc[i][j] += a[i] * w[j];
        }
        __syncthreads();
    }
    #pragma unroll
    for (int i = 0; i < 4; i++) {
        int row = rowBase + ty * 4 + i;
        if (row >= n) continue;
        #pragma unroll
        for (int j = 0; j < CJ; j++) {
            int c = tx + 16 * j;
            float v = acc[i][j];
            if (BIAS) v += bias[c];
            if (RELU) v = fmaxf(v, 0.f);
            if (SKIP) v += skip[row * M + c];
            C[row * M + c] = v;
        }
    }
}

// ---------------- edge pass A: attention logits e + per-dst atomicMax ----------------
__global__ void k_edgeA(const float* __restrict__ attrc, const float* __restrict__ attrp,
                        const int* __restrict__ etype, const int* __restrict__ rid,
                        const int* __restrict__ src, const int* __restrict__ dst,
                        const float* __restrict__ attn, int E) {
    __shared__ float sT[44 * HO];
    __shared__ float sA[HO];
    for (int i = threadIdx.x; i < 44 * HO; i += blockDim.x) sT[i] = g_tab[i];
    for (int i = threadIdx.x; i < HO; i += blockDim.x) sA[i] = attn[i];
    __syncthreads();
    const float* sR  = sT + 7 * HO;
    const float* sRC = sT + 38 * HO;
    const float* sRP = sT + 40 * HO;
    const float* sB  = sT + 43 * HO;
    int lane = threadIdx.x & 31;
    int warp = (blockIdx.x * blockDim.x + threadIdx.x) >> 5;
    int nw = (gridDim.x * blockDim.x) >> 5;
    for (int e = warp; e < E; e += nw) {
        int s = src[e], d = dst[e];
        int et = etype[e], rr = rid[e];
        float rc0 = attrc[e * 2 + 0], rc1 = attrc[e * 2 + 1];
        float rp0 = attrp[e * 3 + 0], rp1 = attrp[e * 3 + 1], rp2 = attrp[e * 3 + 2];
        const float* te = sT + et * HO;
        const float* re = sR + rr * HO;
        float p0 = 0.f, p1 = 0.f;
        #pragma unroll
        for (int j = 0; j < 4; j++) {
            int c = lane + 32 * j;
            float v = g_fni[s * HO + c] + g_fnj[d * HO + c] + te[c] + re[c]
                    + rc0 * sRC[c] + rc1 * sRC[HO + c]
                    + rp0 * sRP[c] + rp1 * sRP[HO + c] + rp2 * sRP[2 * HO + c]
                    + sB[c];
            v = (v > 0.f) ? v : 0.2f * v;  // leaky_relu(0.2)
            float pv = v * sA[c];
            if (j < 2) p0 += pv; else p1 += pv;
        }
        #pragma unroll
        for (int o = 16; o > 0; o >>= 1) {
            p0 += __shfl_xor_sync(0xffffffffu, p0, o);
            p1 += __shfl_xor_sync(0xffffffffu, p1, o);
        }
        if (lane == 0) {
            g_e[e * 2 + 0] = p0;
            g_e[e * 2 + 1] = p1;
            atomicMax(&g_nmax[d * 2 + 0], encf(p0));
            atomicMax(&g_nmax[d * 2 + 1], encf(p1));
        }
    }
}

// ---------------- edge pass B: exp + per-dst sum ----------------
__global__ void k_edgeB(const int* __restrict__ dst, int E) {
    int e = blockIdx.x * blockDim.x + threadIdx.x;
    if (e >= E) return;
    int d = dst[e];
    #pragma unroll
    for (int h = 0; h < 2; h++) {
        float m = decf(g_nmax[d * 2 + h]);
        float ex = __expf(g_e[e * 2 + h] - m);
        g_ex[e * 2 + h] = ex;
        atomicAdd(&g_nsum[d * 2 + h], ex);
    }
}

// ---------------- edge pass C: weighted scatter to h_att ----------------
__global__ void k_edgeC(const int* __restrict__ src, const int* __restrict__ dst, int E) {
    int lane = threadIdx.x & 31;
    int e = (blockIdx.x * blockDim.x + threadIdx.x) >> 5;
    if (e >= E) return;
    int s = src[e], d = dst[e];
    float a0 = g_ex[e * 2 + 0] / (g_nsum[d * 2 + 0] + 1e-9f);
    float a1 = g_ex[e * 2 + 1] / (g_nsum[d * 2 + 1] + 1e-9f);
    #pragma unroll
    for (int j = 0; j < 4; j++) {
        int c = lane + 32 * j;
        float al = (j < 2) ? a0 : a1;
        atomicAdd(&g_hatt[d * HO + c], al * g_hw[s * HO + c]);
    }
}

// ---------------- pooling + output ----------------
__device__ __forceinline__ float getFeat(int node, int f, const float* __restrict__ feat) {
    if (f < 10) return feat[node * 10 + f];
    int a = (f - 10) >> 6, c = (f - 10) & 63;
    return g_h[a][node * HID + c];
}

__global__ void k_zero_pool() {
    int i = blockIdx.x * blockDim.x + threadIdx.x;
    if (i < 8 * NFEAT) g_gmax[i] = 0u;
}

__global__ void k_pool(const float* __restrict__ feat, int npg) {
    int b = blockIdx.x >> 5;
    int part = blockIdx.x & 31;
    int t = threadIdx.x;
    if (t >= NFEAT) return;
    int per = (npg + 31) / 32;
    int n0 = part * per;
    int n1 = min(n0 + per, npg);
    float m = -3.4e38f;
    for (int nn = n0; nn < n1; nn++)
        m = fmaxf(m, getFeat(b * npg + nn, t, feat));
    if (n1 > n0) atomicMax(&g_gmax[b * NFEAT + t], encf(m));
}

__global__ void k_out(const float* __restrict__ feat, float* __restrict__ out, int npg) {
    int idx = blockIdx.x * blockDim.x + threadIdx.x;
    int tot = 8 * npg * (2 * NFEAT);
    if (idx >= tot) return;
    int c = idx % (2 * NFEAT);
    int nn = idx / (2 * NFEAT);      // global node index (b*npg + n)
    int b = nn / npg;
    float v;
    if (c < NFEAT) v = getFeat(nn, c, feat);
    else           v = decf(g_gmax[b * NFEAT + (c - NFEAT)]);
    out[idx] = v;
}

// ---------------- launch ----------------
extern "C" void kernel_launch(void* const* d_in, const int* in_sizes, int n_in,
                              void* d_out, int out_size) {
    const float* feat  = (const float*)d_in[0];
    const float* attrc = (const float*)d_in[1];
    const float* attrp = (const float*)d_in[2];
    const float* etemb = (const float*)d_in[3];
    const float* ridemb= (const float*)d_in[4];
    const float* rcW   = (const float*)d_in[5];
    const float* rcb   = (const float*)d_in[6];
    const float* rpW   = (const float*)d_in[7];
    const float* rpb   = (const float*)d_in[8];
    const float* feW0  = (const float*)d_in[9];
    const float* feb0  = (const float*)d_in[10];
    const float* feW1  = (const float*)d_in[11];
    const float* feb1  = (const float*)d_in[12];
    const float* Wni   = (const float*)d_in[13];
    const float* Wnj   = (const float*)d_in[14];
    const float* Wfij  = (const float*)d_in[15];
    const float* Wnode = (const float*)d_in[16];
    const float* attn  = (const float*)d_in[17];
    const float* ebias = (const float*)d_in[18];
    const float* Wm0   = (const float*)d_in[19];
    const float* bm0   = (const float*)d_in[20];
    const float* Wm1   = (const float*)d_in[21];
    const float* bm1   = (const float*)d_in[22];
    const int* src   = (const int*)d_in[23];
    const int* dst   = (const int*)d_in[24];
    const int* etype = (const int*)d_in[25];
    const int* rid   = (const int*)d_in[26];

    int N = in_sizes[0] / 10;
    int E = in_sizes[23];
    int npg = N / 8;
    float* out = (float*)d_out;

    void* p;
    cudaGetSymbolAddress(&p, g_h);    float* hbase = (float*)p;
    cudaGetSymbolAddress(&p, g_fni);  float* fni   = (float*)p;
    cudaGetSymbolAddress(&p, g_fnj);  float* fnj   = (float*)p;
    cudaGetSymbolAddress(&p, g_hw);   float* hw    = (float*)p;
    cudaGetSymbolAddress(&p, g_hatt); float* hatt  = (float*)p;
    cudaGetSymbolAddress(&p, g_z);    float* zb    = (float*)p;

    int gb = (N + 63) / 64;

    k_h0<<<512, 256>>>(feat, feW0, feb0, feW1, feb1, N);

    for (int l = 0; l < NLAYERS; l++) {
        const float* hl  = hbase + (size_t)l * NMAX * HID;
        float* hlnext    = hbase + (size_t)(l + 1) * NMAX * HID;

        k_tables<<<44, 128>>>(etemb, ridemb, rcW, rpW, rcb, rpb,
                              Wfij + l * HID * HO, ebias + l * HO);
        k_zero_layer<<<(N * HO + 255) / 256, 256>>>(N);

        k_gemm<64, 128, false, false, false><<<gb, 256>>>(hl, Wni + l * HID * HO, nullptr, nullptr, fni, N);
        k_gemm<64, 128, false, false, false><<<gb, 256>>>(hl, Wnj + l * HID * HO, nullptr, nullptr, fnj, N);
        k_gemm<64, 128, false, false, false><<<gb, 256>>>(hl, Wnode + l * HID * HO, nullptr, nullptr, hw, N);

        k_edgeA<<<1184, 256>>>(attrc, attrp, etype, rid, src, dst, attn + l * HO, E);
        k_edgeB<<<(E + 255) / 256, 256>>>(dst, E);
        k_edgeC<<<(E + 7) / 8, 256>>>(src, dst, E);

        k_gemm<128, 128, true, false, true><<<gb, 256>>>(hatt, Wm0 + l * HO * HO, bm0 + l * HO, nullptr, zb, N);
        k_gemm<128, 64, false, true, true><<<gb, 256>>>(zb, Wm1 + l * HO * HID, bm1 + l * HID, hl, hlnext, N);
    }

    k_zero_pool<<<9, 256>>>();
    k_pool<<<256, 288>>>(feat, npg);
    k_out<<<(8 * npg * 2 * NFEAT + 255) / 256, 256>>>(feat, out, npg);
}